// round 11
// baseline (speedup 1.0000x reference)
#include <cuda_runtime.h>
#include <math_constants.h>

#define HH 96
#define WW 128
#define CC 21
#define CPAD 24
#define NN (HH*WW)
#define RR 12
#define TAPS (2*RR+1)
#define NUM_ITER 5
#define GRIDN 128
#define NT 1024
#define GC 3            // channels per group (8 groups * 3 = 24 padded)
#define TROWS (RR + WW + RR)   // 152 tile rows (halo zero-padded)

// scratch (allocation-free rule: __device__ globals). Padded stride-24 layout.
__device__ float g_q[NN*CPAD];            // [h][w][c24]
__device__ float g_tmp[NN*CPAD];          // blur-x result (pads are 0)
__device__ volatile unsigned g_flags[GRIDN]; // distributed barrier flags (monotonic)

// Gaussian weights exp(-d^2/18), d = idx-12. Compile-time immediates.
#define GW_LIST { \
    0.00033546263f, 0.00120386f, 0.00386592f, 0.011108997f, 0.02856550f, \
    0.06572853f, 0.13533528f, 0.24935210f, 0.41111214f, 0.60653066f, \
    0.80073740f, 0.94595947f, 1.0f, 0.94595947f, 0.80073740f, \
    0.60653066f, 0.41111214f, 0.24935210f, 0.13533528f, 0.06572853f, \
    0.02856550f, 0.011108997f, 0.00386592f, 0.00120386f, 0.00033546263f }

// ---------------------------------------------------------------------------
// Persistent kernel, 1024 threads: thread = (pixel, channel-group).
// g = t&7 owns channels [3g, 3g+3). Blur loops fully unrolled with immediate
// weights; tile has zero halos so there are no bounds checks anywhere.
// Distributed-flag grid barrier (128 blocks <= SM count, wave-1 co-resident).
// Bilateral kernel & rgb are dead (source bug uses spatial_out twice).
// ---------------------------------------------------------------------------
__global__ __launch_bounds__(NT) void crf_kernel(
    const float* __restrict__ u,
    const float* __restrict__ sw,
    const float* __restrict__ bw,
    const float* __restrict__ compat,
    float* __restrict__ out)
{
    __shared__ __align__(16) float tile[TROWS][CPAD];  // zero halos rows [0,12),[140,152)
    __shared__ __align__(16) float stile[HH][CPAD];    // normalized blur output
    __shared__ __align__(16) float wc[CC][CPAD];       // compat @ (sw+bw), zero-padded
    __shared__ float snx[WW], sny[HH];

    const float GW[TAPS] = GW_LIST;   // folds to immediates under full unroll

    const int b  = blockIdx.x;
    const int t  = threadIdx.x;
    const int g  = t & 7;
    const int cb = GC * g;            // channel base: 0,3,...,21

    const unsigned base = g_flags[b]; // equal across blocks at launch boundary
    unsigned nb = 1;                  // next barrier index

    // ---- one-time tables ----
    if (t < CC * CC) {
        int r = t / CC, c = t % CC;
        float s = 0.f;
        #pragma unroll
        for (int k = 0; k < CC; k++)
            s += compat[r * CC + k] * (sw[k * CC + c] + bw[k * CC + c]);
        wc[r][c] = s;
    }
    if (t < CC) { wc[t][21] = 0.f; wc[t][22] = 0.f; wc[t][23] = 0.f; }
    if (t < WW) {
        float s = 0.f;
        #pragma unroll
        for (int d = 0; d < TAPS; d++) { int xx = t - RR + d; if (xx >= 0 && xx < WW) s += GW[d]; }
        snx[t] = s;
    }
    if (t < HH) {
        float s = 0.f;
        #pragma unroll
        for (int d = 0; d < TAPS; d++) { int yy = t - RR + d; if (yy >= 0 && yy < HH) s += GW[d]; }
        sny[t] = s;
    }
    // zero static halos: rows [0,RR) and [RR+WW, TROWS)
    {
        int nh = 2 * RR * CPAD;       // 576 words
        if (t < nh) {
            int r = t / CPAD, c = t % CPAD;
            int row = (r < RR) ? r : (RR + WW + (r - RR));
            tile[row][c] = 0.f;
        }
    }
    __syncthreads();

    for (int it = 0; it < NUM_ITER; it++) {
        // ============ row phase: block=row b, thread=(x, g) ============
        if (b < HH) {
            const int x = t >> 3;
            float v[GC];
            if (it == 0) {
                const float* qp = u + (b * WW + x) * CC;
                #pragma unroll
                for (int j = 0; j < GC; j++) {
                    int c = cb + j;
                    v[j] = (c < CC) ? qp[c] : -CUDART_INF_F;
                }
            } else {
                const float* qp = g_q + (b * WW + x) * CPAD + cb;
                #pragma unroll
                for (int j = 0; j < GC; j++)
                    v[j] = (cb + j < CC) ? qp[j] : -CUDART_INF_F;
            }
            // cooperative softmax across the 8 group-lanes of this pixel
            float m = fmaxf(fmaxf(v[0], v[1]), v[2]);
            m = fmaxf(m, __shfl_xor_sync(0xffffffffu, m, 1));
            m = fmaxf(m, __shfl_xor_sync(0xffffffffu, m, 2));
            m = fmaxf(m, __shfl_xor_sync(0xffffffffu, m, 4));
            float s = 0.f;
            #pragma unroll
            for (int j = 0; j < GC; j++) { v[j] = __expf(v[j] - m); s += v[j]; }
            s += __shfl_xor_sync(0xffffffffu, s, 1);
            s += __shfl_xor_sync(0xffffffffu, s, 2);
            s += __shfl_xor_sync(0xffffffffu, s, 4);
            const float inv = 1.0f / s;
            tile[RR + x][cb + 0] = v[0] * inv;   // pads: exp(-inf)=0
            tile[RR + x][cb + 1] = v[1] * inv;
            tile[RR + x][cb + 2] = v[2] * inv;
            __syncthreads();

            // fully-unrolled 25-tap blur, immediate weights, no bounds
            float a0 = 0.f, a1 = 0.f, a2 = 0.f;
            const float* r = &tile[x][cb];       // tap d -> pixel x-12+d
            #pragma unroll
            for (int d = 0; d < TAPS; d++) {
                a0 += GW[d] * r[d * CPAD + 0];
                a1 += GW[d] * r[d * CPAD + 1];
                a2 += GW[d] * r[d * CPAD + 2];
            }
            float* op = g_tmp + (b * WW + x) * CPAD + cb;
            op[0] = a0; op[1] = a1; op[2] = a2;
        }
        // -------- grid barrier (distributed flags) --------
        __syncthreads();
        if (t == 0) { __threadfence(); g_flags[b] = base + nb; }
        if (t < GRIDN) { while (g_flags[t] < base + nb) { } __threadfence(); }
        nb++;
        __syncthreads();

        // ============ col phase: block=column b, thread=(y, g) ============
        {
            const int x = b;
            const int y = t >> 3;           // 0..127 (warp-uniform act)
            if (y < HH) {
                const float* ip = g_tmp + (y * WW + x) * CPAD + cb;
                tile[RR + y][cb + 0] = ip[0];
                tile[RR + y][cb + 1] = ip[1];
                tile[RR + y][cb + 2] = ip[2];
            } else if (y < HH + RR) {       // zero rows 96..107 (read by blur)
                tile[RR + y][cb + 0] = 0.f;
                tile[RR + y][cb + 1] = 0.f;
                tile[RR + y][cb + 2] = 0.f;
            }
            __syncthreads();
            if (y < HH) {
                float a0 = 0.f, a1 = 0.f, a2 = 0.f;
                const float* r = &tile[y][cb];
                #pragma unroll
                for (int d = 0; d < TAPS; d++) {
                    a0 += GW[d] * r[d * CPAD + 0];
                    a1 += GW[d] * r[d * CPAD + 1];
                    a2 += GW[d] * r[d * CPAD + 2];
                }
                const float invn = 1.0f / (snx[x] * sny[y]);
                stile[y][cb + 0] = a0 * invn;
                stile[y][cb + 1] = a1 * invn;
                stile[y][cb + 2] = a2 * invn;
            }
            __syncwarp();   // stile row y written & read within one warp
            if (y < HH) {
                float4 sv[6];
                const float4* sr = (const float4*)&stile[y][0];
                #pragma unroll
                for (int k = 0; k < 6; k++) sv[k] = sr[k];   // pads are 0

                const float* up = u + (y * WW + x) * CC;
                const bool last = (it == NUM_ITER - 1);
                float* qrow = g_q + (y * WW + x) * CPAD;
                float* orow = out + (x * HH + y) * CC;
                #pragma unroll
                for (int j = 0; j < GC; j++) {
                    int cc = cb + j;
                    if (cc < CC) {
                        const float4* wr = (const float4*)&wc[cc][0];  // broadcast
                        float a = 0.f;
                        #pragma unroll
                        for (int k = 0; k < 6; k++) {
                            float4 w4 = wr[k];
                            a += w4.x * sv[k].x + w4.y * sv[k].y
                               + w4.z * sv[k].z + w4.w * sv[k].w;
                        }
                        float val = up[cc] - a;
                        if (last) orow[cc] = val; else qrow[cc] = val;
                    }
                }
            }
        }
        if (it < NUM_ITER - 1) {
            // -------- grid barrier (distributed flags) --------
            __syncthreads();
            if (t == 0) { __threadfence(); g_flags[b] = base + nb; }
            if (t < GRIDN) { while (g_flags[t] < base + nb) { } __threadfence(); }
            nb++;
            __syncthreads();
        }
    }
}

// ---------------------------------------------------------------------------
extern "C" void kernel_launch(void* const* d_in, const int* in_sizes, int n_in,
                              void* d_out, int out_size) {
    const float* unaries = (const float*)d_in[0];   // (1,96,128,21)
    // d_in[1] = rgb — dead: bilateral filter output is unused in the source
    const float* sw      = (const float*)d_in[2];   // (21,21)
    const float* bw      = (const float*)d_in[3];   // (21,21)
    const float* compat  = (const float*)d_in[4];   // (21,21)
    float* out           = (float*)d_out;           // (1,128,96,21)

    crf_kernel<<<GRIDN, NT>>>(unaries, sw, bw, compat, out);
}

// round 16
// speedup vs baseline: 1.4522x; 1.4522x over previous
#include <cuda_runtime.h>
#include <math_constants.h>

#define HH 96
#define WW 128
#define CC 21
#define CPAD 24
#define NN (HH*WW)
#define RR 12
#define TAPS (2*RR+1)
#define NUM_ITER 5
#define GRIDN 128
#define NT 1024
#define GC 3            // channels per group (8 groups * 3 = 24 padded)
#define TROWS (RR + WW + RR)   // 152 tile rows (halo zero-padded)

// scratch (allocation-free rule: __device__ globals). Padded stride-24 layout.
__device__ float g_q[NN*CPAD];      // [h][w][c24]
__device__ float g_tmp[NN*CPAD];    // blur-x result (pads are 0)
__device__ unsigned g_count;        // barrier arrival counter (self-resetting)
__device__ volatile unsigned g_gen; // barrier generation (monotonic)

// Gaussian weights exp(-d^2/18), d = idx-12. Compile-time immediates.
#define GW_LIST { \
    0.00033546263f, 0.00120386f, 0.00386592f, 0.011108997f, 0.02856550f, \
    0.06572853f, 0.13533528f, 0.24935210f, 0.41111214f, 0.60653066f, \
    0.80073740f, 0.94595947f, 1.0f, 0.94595947f, 0.80073740f, \
    0.60653066f, 0.41111214f, 0.24935210f, 0.13533528f, 0.06572853f, \
    0.02856550f, 0.011108997f, 0.00386592f, 0.00120386f, 0.00033546263f }

// ---------------------------------------------------------------------------
// Central-flag grid barrier (measured good in R8 @59.9us): one thread per
// block bumps a counter; ONE thread polls ONE L2 line. GRIDN=128 <= SM count
// so all blocks are wave-1 co-resident. gen is monotonic -> replay-safe.
// ---------------------------------------------------------------------------
__device__ __forceinline__ void grid_barrier() {
    __syncthreads();
    if (threadIdx.x == 0) {
        __threadfence();
        unsigned gen = g_gen;
        if (atomicAdd(&g_count, 1u) == GRIDN - 1) {
            g_count = 0;
            __threadfence();
            g_gen = gen + 1;
        } else {
            while (g_gen == gen) { }
            __threadfence();
        }
    }
    __syncthreads();
}

// ---------------------------------------------------------------------------
// Persistent kernel, 1024 threads: thread = (pixel, channel-group).
// g = t&7 owns channels [3g, 3g+3). Blur fully unrolled, immediate weights,
// zero-halo tile (no bounds checks). Bilateral kernel & rgb are dead
// (source bug uses spatial_out twice).
// ---------------------------------------------------------------------------
__global__ __launch_bounds__(NT) void crf_kernel(
    const float* __restrict__ u,
    const float* __restrict__ sw,
    const float* __restrict__ bw,
    const float* __restrict__ compat,
    float* __restrict__ out)
{
    __shared__ __align__(16) float tile[TROWS][CPAD];  // zero halos [0,12),[140,152)
    __shared__ __align__(16) float stile[HH][CPAD];    // normalized blur output
    __shared__ __align__(16) float wc[CC][CPAD];       // compat @ (sw+bw), zero-padded
    __shared__ float snx[WW], sny[HH];

    const float GW[TAPS] = GW_LIST;   // folds to FFMA immediates under full unroll

    const int b  = blockIdx.x;
    const int t  = threadIdx.x;
    const int g  = t & 7;
    const int cb = GC * g;            // channel base: 0,3,...,21

    // ---- one-time tables ----
    if (t < CC * CC) {
        int r = t / CC, c = t % CC;
        float s = 0.f;
        #pragma unroll
        for (int k = 0; k < CC; k++)
            s += compat[r * CC + k] * (sw[k * CC + c] + bw[k * CC + c]);
        wc[r][c] = s;
    }
    if (t < CC) { wc[t][21] = 0.f; wc[t][22] = 0.f; wc[t][23] = 0.f; }
    if (t < WW) {
        float s = 0.f;
        #pragma unroll
        for (int d = 0; d < TAPS; d++) { int xx = t - RR + d; if (xx >= 0 && xx < WW) s += GW[d]; }
        snx[t] = s;
    }
    if (t < HH) {
        float s = 0.f;
        #pragma unroll
        for (int d = 0; d < TAPS; d++) { int yy = t - RR + d; if (yy >= 0 && yy < HH) s += GW[d]; }
        sny[t] = s;
    }
    // zero static halos: rows [0,RR) and [RR+WW, TROWS)
    {
        int nh = 2 * RR * CPAD;       // 576 words
        if (t < nh) {
            int r = t / CPAD, c = t % CPAD;
            int row = (r < RR) ? r : (RR + WW + (r - RR));
            tile[row][c] = 0.f;
        }
    }
    __syncthreads();

    for (int it = 0; it < NUM_ITER; it++) {
        // ============ row phase: block=row b, thread=(x, g) ============
        if (b < HH) {
            const int x = t >> 3;
            float v[GC];
            if (it == 0) {
                const float* qp = u + (b * WW + x) * CC;
                #pragma unroll
                for (int j = 0; j < GC; j++) {
                    int c = cb + j;
                    v[j] = (c < CC) ? qp[c] : -CUDART_INF_F;
                }
            } else {
                const float* qp = g_q + (b * WW + x) * CPAD + cb;
                #pragma unroll
                for (int j = 0; j < GC; j++)
                    v[j] = (cb + j < CC) ? qp[j] : -CUDART_INF_F;
            }
            // cooperative softmax across the 8 group-lanes of this pixel
            float m = fmaxf(fmaxf(v[0], v[1]), v[2]);
            m = fmaxf(m, __shfl_xor_sync(0xffffffffu, m, 1));
            m = fmaxf(m, __shfl_xor_sync(0xffffffffu, m, 2));
            m = fmaxf(m, __shfl_xor_sync(0xffffffffu, m, 4));
            float s = 0.f;
            #pragma unroll
            for (int j = 0; j < GC; j++) { v[j] = __expf(v[j] - m); s += v[j]; }
            s += __shfl_xor_sync(0xffffffffu, s, 1);
            s += __shfl_xor_sync(0xffffffffu, s, 2);
            s += __shfl_xor_sync(0xffffffffu, s, 4);
            const float inv = 1.0f / s;
            tile[RR + x][cb + 0] = v[0] * inv;   // pads: exp(-inf)=0
            tile[RR + x][cb + 1] = v[1] * inv;
            tile[RR + x][cb + 2] = v[2] * inv;
            __syncthreads();

            // fully-unrolled 25-tap blur, immediate weights, no bounds
            float a0 = 0.f, a1 = 0.f, a2 = 0.f;
            const float* r = &tile[x][cb];       // tap d -> pixel x-12+d
            #pragma unroll
            for (int d = 0; d < TAPS; d++) {
                a0 += GW[d] * r[d * CPAD + 0];
                a1 += GW[d] * r[d * CPAD + 1];
                a2 += GW[d] * r[d * CPAD + 2];
            }
            float* op = g_tmp + (b * WW + x) * CPAD + cb;
            op[0] = a0; op[1] = a1; op[2] = a2;
        }
        grid_barrier();

        // ============ col phase: block=column b, thread=(y, g) ============
        {
            const int x = b;
            const int y = t >> 3;           // 0..127 (warp-uniform act)
            if (y < HH) {
                const float* ip = g_tmp + (y * WW + x) * CPAD + cb;
                tile[RR + y][cb + 0] = ip[0];
                tile[RR + y][cb + 1] = ip[1];
                tile[RR + y][cb + 2] = ip[2];
            } else if (y < HH + RR) {       // zero rows 96..107 (read by blur)
                tile[RR + y][cb + 0] = 0.f;
                tile[RR + y][cb + 1] = 0.f;
                tile[RR + y][cb + 2] = 0.f;
            }
            __syncthreads();
            if (y < HH) {
                float a0 = 0.f, a1 = 0.f, a2 = 0.f;
                const float* r = &tile[y][cb];
                #pragma unroll
                for (int d = 0; d < TAPS; d++) {
                    a0 += GW[d] * r[d * CPAD + 0];
                    a1 += GW[d] * r[d * CPAD + 1];
                    a2 += GW[d] * r[d * CPAD + 2];
                }
                const float invn = 1.0f / (snx[x] * sny[y]);
                stile[y][cb + 0] = a0 * invn;
                stile[y][cb + 1] = a1 * invn;
                stile[y][cb + 2] = a2 * invn;
            }
            __syncwarp();   // stile row y written & read within one warp
            if (y < HH) {
                float4 sv[6];
                const float4* sr = (const float4*)&stile[y][0];
                #pragma unroll
                for (int k = 0; k < 6; k++) sv[k] = sr[k];   // pads are 0

                const float* up = u + (y * WW + x) * CC;
                const bool last = (it == NUM_ITER - 1);
                float* qrow = g_q + (y * WW + x) * CPAD;
                float* orow = out + (x * HH + y) * CC;
                #pragma unroll
                for (int j = 0; j < GC; j++) {
                    int cc = cb + j;
                    if (cc < CC) {
                        const float4* wr = (const float4*)&wc[cc][0];  // broadcast
                        float a = 0.f;
                        #pragma unroll
                        for (int k = 0; k < 6; k++) {
                            float4 w4 = wr[k];
                            a += w4.x * sv[k].x + w4.y * sv[k].y
                               + w4.z * sv[k].z + w4.w * sv[k].w;
                        }
                        float val = up[cc] - a;
                        if (last) orow[cc] = val; else qrow[cc] = val;
                    }
                }
            }
        }
        if (it < NUM_ITER - 1) grid_barrier();
    }
}

// ---------------------------------------------------------------------------
extern "C" void kernel_launch(void* const* d_in, const int* in_sizes, int n_in,
                              void* d_out, int out_size) {
    const float* unaries = (const float*)d_in[0];   // (1,96,128,21)
    // d_in[1] = rgb — dead: bilateral filter output is unused in the source
    const float* sw      = (const float*)d_in[2];   // (21,21)
    const float* bw      = (const float*)d_in[3];   // (21,21)
    const float* compat  = (const float*)d_in[4];   // (21,21)
    float* out           = (float*)d_out;           // (1,128,96,21)

    crf_kernel<<<GRIDN, NT>>>(unaries, sw, bw, compat, out);
}